// round 15
// baseline (speedup 1.0000x reference)
#include <cuda_runtime.h>
#include <cuda_bf16.h>
#include <math.h>
#include <stdint.h>

#define NL 8
#define NS 192
#define ND 512
#define NF 2048
#define NB 16
#define EPSF 1e-5f

// ---------------- scratch (static device globals; no allocations) ----------------
__device__ uint32_t d_qfp  [NB*NL*ND*NS];      // packed bf16(hi,lo) q_feat  [b][i*D+d][t]
__device__ uint32_t d_gfp  [NB*NL*ND*NS];      // packed g_feat
__device__ uint32_t d_w0p  [NL*ND*ND];         // packed fc0_w   [i][e][d]
__device__ uint32_t d_qryp [NL*NB*NS*ND];      // packed query   [i][b][t][e]
__device__ uint32_t d_keyp [NL*NB*NS*ND];      // packed key     [i][b][s][e]
__device__ float d_sigse[NL*NS*NS];            // sigmoid(score_embed)
__device__ float d_x    [NL*512*NS];           // [i][r=2qk+branch][S]
__device__ float d_bn1m[NL], d_bn1r[NL];
__device__ float d_u    [NL*512*NF];           // fc2 output
__device__ float d_bn2m[NL*NF], d_bn2r[NL*NF];
__device__ float d_y    [NL*512];              // fc3 per-row output

// ---------------- bf16 split-pack helpers ----------------
// pack x ~= hi + lo (both bf16): low16 = hi, high16 = lo.
// 2-pass mma: pass1 A=(hi,lo) x B=(hi,hi) -> hiA*hiB + loA*hiB
//             pass2 A=(hi,hi) x B=(lo,0)  -> hiA*loB   (drops only loA*loB ~2^-18)
__device__ __forceinline__ uint32_t packsplit(float x){
    __nv_bfloat16 h = __float2bfloat16(x);
    float r = x - __bfloat162float(h);
    __nv_bfloat16 l = __float2bfloat16(r);
    return (uint32_t)__bfloat16_as_ushort(h) | ((uint32_t)__bfloat16_as_ushort(l) << 16);
}
__device__ __forceinline__ uint32_t duphi(uint32_t p){ return __byte_perm(p, p, 0x1010); } // (hi,hi)
__device__ __forceinline__ uint32_t lozero(uint32_t p){ return __byte_perm(p, 0, 0x4432); } // (lo,0)

__device__ __forceinline__ void mma_bf16(float* c, const uint32_t* a, const uint32_t* b){
    asm volatile("mma.sync.aligned.m16n8k16.row.col.f32.bf16.bf16.f32 "
        "{%0,%1,%2,%3}, {%4,%5,%6,%7}, {%8,%9}, {%0,%1,%2,%3};"
        : "+f"(c[0]),"+f"(c[1]),"+f"(c[2]),"+f"(c[3])
        : "r"(a[0]),"r"(a[1]),"r"(a[2]),"r"(a[3]), "r"(b[0]),"r"(b[1]));
}

// cp.async helpers (16B)
__device__ __forceinline__ void cpasync16(void* smem_dst, const void* gmem_src){
    uint32_t sa = (uint32_t)__cvta_generic_to_shared(smem_dst);
    asm volatile("cp.async.cg.shared.global [%0], [%1], 16;" :: "r"(sa), "l"(gmem_src));
}
__device__ __forceinline__ void cpasync_commit(){ asm volatile("cp.async.commit_group;"); }
__device__ __forceinline__ void cpasync_wait1(){ asm volatile("cp.async.wait_group 1;"); }
__device__ __forceinline__ void cpasync_wait0(){ asm volatile("cp.async.wait_group 0;"); }

// ---------------- elementwise split-pack ----------------
__global__ void k_split(const float* __restrict__ src, uint32_t* __restrict__ dst, int n){
    int idx = blockIdx.x*256 + threadIdx.x;
    if (idx < n) dst[idx] = packsplit(src[idx]);
}

// ---------------- precompute sigmoid(score_embed) ----------------
__global__ void k_sigse(const float* __restrict__ se){
    int idx = blockIdx.x*256 + threadIdx.x;
    if (idx < NL*NS*NS) d_sigse[idx] = 1.f/(1.f+expf(-se[idx]));
}

// ---------------- fc0 projection (2-pass bf16-split mma, cp.async double-buffered)
// out[i][b][t][e] = sum_d feat[b][i*D+d][t] * w0[i][e][d] + b0[i][e]
// grid (4 e-tiles, B, L), 512 threads (16 warps). CTA: 192 t x 128 e, 16 elems/chunk.
// warp w: mw=w>>2 -> t-base mw*48 (3 m-tiles), nw=w&3 -> e-base nw*32 (4 n-tiles).
#define PAS 200
__global__ void __launch_bounds__(512) k_proj(const uint32_t* __restrict__ featP,
                       const float* __restrict__ b0, uint32_t* __restrict__ outP){
    const int i = blockIdx.z, b = blockIdx.y, e0 = blockIdx.x*128;
    const int tid = threadIdx.x;
    const int w = tid>>5, lane = tid&31;
    const int g = lane>>2, c = lane&3;
    const int mw = w>>2, nw = w&3;
    __shared__ uint32_t As[2][16*PAS];    // [kk][t]   2 x 12800B
    __shared__ uint32_t Bs[2][128*20];    // [e][kk]   2 x 10240B -> 46KB static
    float acc[3][4][4];
#pragma unroll
    for (int mt=0;mt<3;mt++)
#pragma unroll
        for (int nt=0;nt<4;nt++)
#pragma unroll
            for (int r=0;r<4;r++) acc[mt][nt][r]=0.f;
    const uint32_t* fbase = featP + (size_t)(b*(ND*NL) + i*ND)*NS;
    const uint32_t* wbase = d_w0p + (size_t)i*ND*ND + (size_t)e0*ND;
    const int tb = mw*48;

    auto stageFull = [&](int ch, int bufi){
        const int kc = ch*16;
        // As: 16 rows x 48 uint4 = 768 ; Bs: 128 rows x 4 uint4 = 512 ; total 1280
        for (int idx = tid; idx < 1280; idx += 512){
            if (idx < 768){
                int kk = idx / 48, j = idx % 48;
                cpasync16(&As[bufi][kk*PAS + j*4], &fbase[(size_t)(kc+kk)*NS + j*4]);
            } else {
                int r2 = idx - 768;
                int ee = r2 >> 2, j = r2 & 3;
                cpasync16(&Bs[bufi][ee*20 + j*4], &wbase[(size_t)ee*ND + kc + j*4]);
            }
        }
        cpasync_commit();
    };

    stageFull(0, 0);
    const int NCH = ND/16;  // 32
    for (int ch = 0; ch < NCH; ch++){
        if (ch + 1 < NCH){ stageFull(ch+1, (ch+1)&1); cpasync_wait1(); }
        else             { cpasync_wait0(); }
        __syncthreads();
        const uint32_t* Ab = As[ch&1];
        const uint32_t* Bb = Bs[ch&1];
#pragma unroll
        for (int ks=0; ks<2; ks++){
            const int k0 = ks*8;
            uint32_t bdup[4][2], blo0[4][2];
#pragma unroll
            for (int nt=0;nt<4;nt++){
                int e = nw*32 + nt*8 + g;
                uint32_t b0r = Bb[e*20 + k0 + c];
                uint32_t b1r = Bb[e*20 + k0 + 4 + c];
                bdup[nt][0] = duphi(b0r);  bdup[nt][1] = duphi(b1r);
                blo0[nt][0] = lozero(b0r); blo0[nt][1] = lozero(b1r);
            }
#pragma unroll
            for (int mt=0;mt<3;mt++){
                int r = tb + mt*16 + g;
                uint32_t araw[4], adup[4];
                araw[0] = Ab[(k0+c)*PAS + r];
                araw[1] = Ab[(k0+c)*PAS + r + 8];
                araw[2] = Ab[(k0+4+c)*PAS + r];
                araw[3] = Ab[(k0+4+c)*PAS + r + 8];
#pragma unroll
                for (int j=0;j<4;j++) adup[j] = duphi(araw[j]);
#pragma unroll
                for (int nt=0;nt<4;nt++){
                    mma_bf16(acc[mt][nt], araw, bdup[nt]);
                    mma_bf16(acc[mt][nt], adup, blo0[nt]);
                }
            }
        }
        __syncthreads();
    }
    // epilogue: + bias, split-pack, store 2 packed elems as uint2
    uint32_t* obase = outP + (size_t)(i*NB+b)*NS*ND;
#pragma unroll
    for (int nt=0;nt<4;nt++){
        int e = e0 + nw*32 + nt*8 + 2*c;
        float b01 = b0[i*ND + e], b11 = b0[i*ND + e + 1];
#pragma unroll
        for (int mt=0;mt<3;mt++){
            int r = tb + mt*16 + g;
            uint2 v0 = make_uint2(packsplit(acc[mt][nt][0] + b01), packsplit(acc[mt][nt][1] + b11));
            uint2 v1 = make_uint2(packsplit(acc[mt][nt][2] + b01), packsplit(acc[mt][nt][3] + b11));
            *reinterpret_cast<uint2*>(&obase[(size_t)r*ND + e])     = v0;
            *reinterpret_cast<uint2*>(&obase[(size_t)(r+8)*ND + e]) = v1;
        }
    }
}

// ---------------- score GEMM (2-pass bf16-split, 3-stage cp.async, ONE barrier/chunk)
// grid (256 qk, L), 512 threads (16 warps). CTA: FULL tile t 192 x s 192, K-chunk 32.
// Pipeline per chunk: wait -> BAR -> stage(ch+2) -> compute(ch). The single BAR proves
// compute(ch-1) finished everywhere, which is the safety condition for overwriting
// buffer (ch+2)%3. Dynamic smem: 3 stages x 2 arrays x 192 x 36 x 4B = 165888 B.
#define STR 36
__global__ void __launch_bounds__(512) k_score(){
    extern __shared__ uint32_t dynsm[];
    const int i = blockIdx.y, qk = blockIdx.x;
    const int q = qk >> 4, k = qk & 15;
    const int tid = threadIdx.x;
    const int w = tid>>5, lane = tid&31;
    const int g = lane>>2, c = lane&3;
    const int mw = w>>2, nw = w&3;
    uint32_t* Asb[3] = { dynsm,            dynsm + 2*NS*STR, dynsm + 4*NS*STR };
    uint32_t* Bsb[3] = { dynsm + NS*STR,   dynsm + 3*NS*STR, dynsm + 5*NS*STR };
    float acc[3][6][4];
#pragma unroll
    for (int mt=0;mt<3;mt++)
#pragma unroll
        for (int nt=0;nt<6;nt++)
#pragma unroll
            for (int r=0;r<4;r++) acc[mt][nt][r]=0.f;
    const uint32_t* qbase = d_qryp + (size_t)(i*NB+q)*NS*ND;
    const uint32_t* kbase = d_keyp + (size_t)(i*NB+k)*NS*ND;
    const int tb = mw*48, sb = nw*48;

    auto stage = [&](int ch, int bufi){
        const int kc = ch*32;
        // As: 192 rows x 8 uint4 = 1536 ; Bs same ; total 3072
        for (int idx = tid; idx < 3072; idx += 512){
            if (idx < 1536){
                int t = idx >> 3, j = idx & 7;
                cpasync16(&Asb[bufi][t*STR + j*4], &qbase[(size_t)t*ND + kc + j*4]);
            } else {
                int r2 = idx - 1536;
                int s = r2 >> 3, j = r2 & 7;
                cpasync16(&Bsb[bufi][s*STR + j*4], &kbase[(size_t)s*ND + kc + j*4]);
            }
        }
        cpasync_commit();
    };

    stage(0, 0);
    stage(1, 1);
    const int NCH = ND/32;  // 16
    for (int ch = 0; ch < NCH; ch++){
        if (ch + 1 < NCH) cpasync_wait1();   // buffer ch complete, ch+1 may be pending
        else              cpasync_wait0();
        __syncthreads();                      // all warps done with compute(ch-1)
        if (ch + 2 < NCH) stage(ch+2, (ch+2)%3);
        const uint32_t* Ab = Asb[ch%3];
        const uint32_t* Bb = Bsb[ch%3];
#pragma unroll
        for (int ks=0; ks<4; ks++){
            const int k0 = ks*8;
            uint32_t bdup[6][2], blo0[6][2];
#pragma unroll
            for (int nt=0;nt<6;nt++){
                int s = sb + nt*8 + g;
                uint32_t b0r = Bb[s*STR + k0 + c];
                uint32_t b1r = Bb[s*STR + k0 + 4 + c];
                bdup[nt][0] = duphi(b0r);  bdup[nt][1] = duphi(b1r);
                blo0[nt][0] = lozero(b0r); blo0[nt][1] = lozero(b1r);
            }
#pragma unroll
            for (int mt=0;mt<3;mt++){
                int t = tb + mt*16 + g;
                uint32_t araw[4], adup[4];
                araw[0] = Ab[t*STR + k0 + c];
                araw[1] = Ab[(t+8)*STR + k0 + c];
                araw[2] = Ab[t*STR + k0 + 4 + c];
                araw[3] = Ab[(t+8)*STR + k0 + 4 + c];
#pragma unroll
                for (int j=0;j<4;j++) adup[j] = duphi(araw[j]);
#pragma unroll
                for (int nt=0;nt<6;nt++){
                    mma_bf16(acc[mt][nt], araw, bdup[nt]);
                    mma_bf16(acc[mt][nt], adup, blo0[nt]);
                }
            }
        }
    }
    __syncthreads();   // protect reduction scratch: aliases buffer 0 = last compute buffer (15%3==0)
    // mask by sigmoid(score_embed): element (row=t, col=s) *= sigse[s*NS + t]
    const float* sbase = d_sigse + (size_t)i*NS*NS;
#pragma unroll
    for (int mt=0;mt<3;mt++){
        int t0v = tb + mt*16 + g, t1v = t0v + 8;
#pragma unroll
        for (int nt=0;nt<6;nt++){
            int sc = sb + nt*8 + 2*c;
            acc[mt][nt][0] *= sbase[(size_t)sc*NS + t0v];
            acc[mt][nt][1] *= sbase[(size_t)(sc+1)*NS + t0v];
            acc[mt][nt][2] *= sbase[(size_t)sc*NS + t1v];
            acc[mt][nt][3] *= sbase[(size_t)(sc+1)*NS + t1v];
        }
    }
    // reduction scratch aliases dynsm (safe after the barrier above)
    float* rowbuf = reinterpret_cast<float*>(dynsm);        // [16][48]
    float* colbuf = rowbuf + 16*48;                          // [16][48]
    // ---- rowmax partial: per warp, max over its 48 s, per t row ----
    float rm[3][2];
#pragma unroll
    for (int mt=0;mt<3;mt++){
        float m0 = fmaxf(acc[mt][0][0], acc[mt][0][1]);
        float m1 = fmaxf(acc[mt][0][2], acc[mt][0][3]);
#pragma unroll
        for (int nt=1;nt<6;nt++){
            m0 = fmaxf(m0, fmaxf(acc[mt][nt][0], acc[mt][nt][1]));
            m1 = fmaxf(m1, fmaxf(acc[mt][nt][2], acc[mt][nt][3]));
        }
        rm[mt][0] = m0; rm[mt][1] = m1;
    }
#pragma unroll
    for (int off=1; off<4; off<<=1)
#pragma unroll
        for (int mt=0;mt<3;mt++){
            rm[mt][0] = fmaxf(rm[mt][0], __shfl_xor_sync(0xffffffffu, rm[mt][0], off));
            rm[mt][1] = fmaxf(rm[mt][1], __shfl_xor_sync(0xffffffffu, rm[mt][1], off));
        }
    if (c == 0){
#pragma unroll
        for (int mt=0;mt<3;mt++){
            rowbuf[w*48 + mt*16 + g]     = rm[mt][0];
            rowbuf[w*48 + mt*16 + g + 8] = rm[mt][1];
        }
    }
    // ---- colmax partial: per warp, max over its 48 t, per s col ----
    float cm[6][2];
#pragma unroll
    for (int nt=0;nt<6;nt++){
        float m0 = fmaxf(acc[0][nt][0], acc[0][nt][2]);
        float m1 = fmaxf(acc[0][nt][1], acc[0][nt][3]);
#pragma unroll
        for (int mt=1;mt<3;mt++){
            m0 = fmaxf(m0, fmaxf(acc[mt][nt][0], acc[mt][nt][2]));
            m1 = fmaxf(m1, fmaxf(acc[mt][nt][1], acc[mt][nt][3]));
        }
        cm[nt][0] = m0; cm[nt][1] = m1;
    }
#pragma unroll
    for (int off=4; off<32; off<<=1)
#pragma unroll
        for (int nt=0;nt<6;nt++){
            cm[nt][0] = fmaxf(cm[nt][0], __shfl_xor_sync(0xffffffffu, cm[nt][0], off));
            cm[nt][1] = fmaxf(cm[nt][1], __shfl_xor_sync(0xffffffffu, cm[nt][1], off));
        }
    if (g == 0){
#pragma unroll
        for (int nt=0;nt<6;nt++){
            colbuf[w*48 + nt*8 + 2*c]     = cm[nt][0];
            colbuf[w*48 + nt*8 + 2*c + 1] = cm[nt][1];
        }
    }
    __syncthreads();
    // final merge: 192 rowmax (over 4 n-warps) + 192 colmax (over 4 m-warps), both direct writes
    for (int idx = tid; idx < 2*NS; idx += 512){
        if (idx < NS){       // rowmax for t row idx: warps w = mw*4 + nw, nw 0..3
            int mwv = idx / 48, j = idx % 48;
            float v = rowbuf[(mwv*4 + 0)*48 + j];
#pragma unroll
            for (int nwv=1; nwv<4; nwv++) v = fmaxf(v, rowbuf[(mwv*4 + nwv)*48 + j]);
            d_x[((size_t)i*512 + 2*qk)*NS + idx] = v;
        } else {             // colmax for s col: warps w = mw*4 + nw, mw 0..3
            int sl = idx - NS;
            int nwv = sl / 48, j = sl % 48;
            float v = colbuf[(0*4 + nwv)*48 + j];
#pragma unroll
            for (int mwv=1; mwv<4; mwv++) v = fmaxf(v, colbuf[(mwv*4 + nwv)*48 + j]);
            d_x[((size_t)i*512 + 2*qk + 1)*NS + sl] = v;
        }
    }
}

// ---------------- bn1 stats (whole-tensor mean/var per layer), double accum
__global__ void k_bn1(){
    const int i = blockIdx.x, tid = threadIdx.x;   // 8 blocks x 512 threads
    const float* p = d_x + (size_t)i*512*NS;
    double s=0.0, sq=0.0;
    for (int idx=tid; idx<512*NS; idx+=512){ double v = p[idx]; s+=v; sq+=v*v; }
    __shared__ double ss[512], sqs[512];
    ss[tid]=s; sqs[tid]=sq; __syncthreads();
    for (int off=256; off; off>>=1){
        if (tid<off){ ss[tid]+=ss[tid+off]; sqs[tid]+=sqs[tid+off]; }
        __syncthreads();
    }
    if (tid==0){
        double n = 512.0*NS;
        double mean = ss[0]/n;
        double var  = sqs[0]/n - mean*mean;
        d_bn1m[i] = (float)mean;
        d_bn1r[i] = (float)rsqrt(var + 1e-5);
    }
}

// ---------------- fc2: u = bn1(x) @ w2^T + b2.  grid (32 f-tiles, 8 r-tiles, L), 256 thr, CTA 64x64.
__global__ void k_fc2(const float* __restrict__ w2, const float* __restrict__ b2,
                      const float* __restrict__ g1, const float* __restrict__ b1){
    const int i = blockIdx.z, r0 = blockIdx.y*64, f0 = blockIdx.x*64;
    const int tid = threadIdx.x, tx = tid&15, ty = tid>>4;
    const float alpha = g1[i]*d_bn1r[i];
    const float beta  = b1[i] - d_bn1m[i]*alpha;
    __shared__ float Xs[64][33], Ws[64][33];
    float acc[4][4];
#pragma unroll
    for (int u=0;u<4;u++)
#pragma unroll
        for (int v=0;v<4;v++) acc[u][v]=0.f;
    const float* xbase = d_x + (size_t)(i*512 + r0)*NS;
    const float* wbase = w2  + (size_t)(i*NF + f0)*NS;
    for (int kc=0; kc<NS; kc+=32){
        for (int idx=tid; idx<64*32; idx+=256){
            int rr = idx>>5, kk = idx&31;
            Xs[rr][kk] = xbase[(size_t)rr*NS + kc+kk]*alpha + beta;
        }
        for (int idx=tid; idx<64*32; idx+=256){
            int ff = idx>>5, kk = idx&31;
            Ws[ff][kk] = wbase[(size_t)ff*NS + kc+kk];
        }
        __syncthreads();
#pragma unroll
        for (int kk=0; kk<32; kk++){
            float a[4], bb[4];
#pragma unroll
            for (int u=0;u<4;u++) a[u]  = Xs[ty*4+u][kk];
#pragma unroll
            for (int v=0;v<4;v++) bb[v] = Ws[tx*4+v][kk];
#pragma unroll
            for (int u=0;u<4;u++)
#pragma unroll
                for (int v=0;v<4;v++) acc[u][v] = fmaf(a[u], bb[v], acc[u][v]);
        }
        __syncthreads();
    }
#pragma unroll
    for (int u=0;u<4;u++){
        int r = r0 + ty*4 + u;
#pragma unroll
        for (int v=0;v<4;v++){
            int f = f0 + tx*4 + v;
            d_u[(size_t)(i*512 + r)*NF + f] = acc[u][v] + b2[i*NF + f];
        }
    }
}

// ---------------- bn2 stats (per-feature mean/var over 512 rows)
__global__ void k_bn2(){
    const int i = blockIdx.y, f0 = blockIdx.x*64;
    const int tid = threadIdx.x, fx = tid&63, rg = tid>>6;
    const float* p = d_u + (size_t)i*512*NF + f0 + fx;
    float s=0.f, sq=0.f;
    for (int r=rg; r<512; r+=4){ float v = p[(size_t)r*NF]; s+=v; sq+=v*v; }
    __shared__ float ss[256], sqs[256];
    ss[tid]=s; sqs[tid]=sq; __syncthreads();
    if (rg==0){
        float S  = ss[fx]  + ss[fx+64]  + ss[fx+128]  + ss[fx+192];
        float SQ = sqs[fx] + sqs[fx+64] + sqs[fx+128] + sqs[fx+192];
        float mean = S/512.f;
        float var  = SQ/512.f - mean*mean;
        d_bn2m[i*NF+f0+fx] = mean;
        d_bn2r[i*NF+f0+fx] = rsqrtf(var + EPSF);
    }
}

// ---------------- fc3: y[row] = relu(bn2(u[row])) . w3   (one warp per row)
__global__ void k_fc3(const float* __restrict__ g2, const float* __restrict__ bb2,
                      const float* __restrict__ w3){
    const int row  = blockIdx.x*8 + (threadIdx.x>>5);   // 512 blocks x 8 warps = 4096 rows
    const int lane = threadIdx.x & 31;
    const int i = row >> 9;
    const float* up = d_u + (size_t)row*NF;
    float s = 0.f;
    for (int f=lane; f<NF; f+=32){
        int gi = i*NF + f;
        float z = g2[gi]*(up[f]-d_bn2m[gi])*d_bn2r[gi] + bb2[gi];
        z = fmaxf(z, 0.f);
        s = fmaf(z, w3[gi], s);
    }
#pragma unroll
    for (int off=16; off; off>>=1) s += __shfl_xor_sync(0xffffffffu, s, off);
    if (lane==0) d_y[row] = s;
}

// ---------------- final: pair-sum, bn3 per layer, accumulate, labels
__global__ void k_final(const float* __restrict__ b3, const float* __restrict__ g3,
                        const float* __restrict__ bb3, const int* __restrict__ targets,
                        float* __restrict__ out, int out_size){
    const int qk = threadIdx.x;   // 256
    __shared__ double ss[256], sqs[256];
    float accum = 0.f;
    for (int i=0;i<NL;i++){
        float p = d_y[i*512 + 2*qk] + d_y[i*512 + 2*qk + 1] + 2.f*b3[i];
        ss[qk] = (double)p; sqs[qk] = (double)p*(double)p;
        __syncthreads();
        for (int off=128; off; off>>=1){
            if (qk<off){ ss[qk]+=ss[qk+off]; sqs[qk]+=sqs[qk+off]; }
            __syncthreads();
        }
        double mean = ss[0]/256.0;
        double var  = sqs[0]/256.0 - mean*mean;
        float rstd  = (float)rsqrt(var + 1e-5);
        accum += g3[i]*((p - (float)mean)*rstd) + bb3[i];
        __syncthreads();   // protect ss/sqs before next layer overwrites
    }
    out[qk] = accum;
    if (out_size >= 512){
        int qq = qk >> 4, kk = qk & 15;
        out[256 + qk] = (targets[qq]==targets[kk]) ? 1.f : 0.f;
    }
}

// ---------------- launcher ----------------
extern "C" void kernel_launch(void* const* d_in, const int* in_sizes, int n_in,
                              void* d_out, int out_size){
    const float* q_feat = (const float*)d_in[0];
    const float* g_feat = (const float*)d_in[1];
    const int*   targets= (const int*)  d_in[2];
    const float* se     = (const float*)d_in[3];
    const float* fc0w   = (const float*)d_in[4];
    const float* fc0b   = (const float*)d_in[5];
    const float* bn1g   = (const float*)d_in[6];
    const float* bn1b   = (const float*)d_in[7];
    const float* fc2w   = (const float*)d_in[8];
    const float* fc2b   = (const float*)d_in[9];
    const float* bn2g   = (const float*)d_in[10];
    const float* bn2b   = (const float*)d_in[11];
    const float* fc3w   = (const float*)d_in[12];
    const float* fc3b   = (const float*)d_in[13];
    const float* bn3g   = (const float*)d_in[14];
    const float* bn3b   = (const float*)d_in[15];
    float* out = (float*)d_out;

    uint32_t *p_qfp, *p_gfp, *p_w0p, *p_qryp, *p_keyp;
    cudaGetSymbolAddress((void**)&p_qfp,  d_qfp);
    cudaGetSymbolAddress((void**)&p_gfp,  d_gfp);
    cudaGetSymbolAddress((void**)&p_w0p,  d_w0p);
    cudaGetSymbolAddress((void**)&p_qryp, d_qryp);
    cudaGetSymbolAddress((void**)&p_keyp, d_keyp);

    const int nfeat = NB*NL*ND*NS;
    const int nw0   = NL*ND*ND;
    const int SCORE_SMEM = 6*NS*STR*4;   // 165888 B (3-stage)

    // context op (not stream-ordered, not captured, no allocation) — idempotent
    cudaFuncSetAttribute(k_score, cudaFuncAttributeMaxDynamicSharedMemorySize, SCORE_SMEM);

    k_sigse<<<(NL*NS*NS+255)/256, 256>>>(se);
    k_split<<<(nfeat+255)/256, 256>>>(q_feat, p_qfp, nfeat);
    k_split<<<(nfeat+255)/256, 256>>>(g_feat, p_gfp, nfeat);
    k_split<<<(nw0+255)/256,   256>>>(fc0w,   p_w0p, nw0);
    k_proj<<<dim3(4, NB, NL), 512>>>(p_qfp, fc0b, p_qryp);
    k_proj<<<dim3(4, NB, NL), 512>>>(p_gfp, fc0b, p_keyp);
    k_score<<<dim3(256, NL), 512, SCORE_SMEM>>>();
    k_bn1<<<NL, 512>>>();
    k_fc2<<<dim3(32, 8, NL), 256>>>(fc2w, fc2b, bn1g, bn1b);
    k_bn2<<<dim3(32, NL), 256>>>();
    k_fc3<<<512, 256>>>(bn2g, bn2b, fc3w);
    k_final<<<1, 256>>>(fc3b, bn3g, bn3b, targets, out, out_size);
}

// round 16
// speedup vs baseline: 1.5152x; 1.5152x over previous
#include <cuda_runtime.h>
#include <cuda_bf16.h>
#include <math.h>
#include <stdint.h>

#define NL 8
#define NS 192
#define ND 512
#define NF 2048
#define NB 16
#define EPSF 1e-5f

// ---------------- scratch (static device globals; no allocations) ----------------
__device__ uint32_t d_qfp  [NB*NL*ND*NS];      // packed bf16(hi,lo) q_feat  [b][i*D+d][t]
__device__ uint32_t d_gfp  [NB*NL*ND*NS];      // packed g_feat
__device__ uint32_t d_w0p  [NL*ND*ND];         // packed fc0_w   [i][e][d]
__device__ uint32_t d_qryp [NL*NB*NS*ND];      // packed query   [i][b][t][e]
__device__ uint32_t d_keyp [NL*NB*NS*ND];      // packed key     [i][b][s][e]
__device__ float d_sigse[NL*NS*NS];            // sigmoid(score_embed)
__device__ float d_x    [NL*512*NS];           // [i][r=2qk+branch][S]
__device__ float d_bn1m[NL], d_bn1r[NL];
__device__ float d_u    [NL*512*NF];           // fc2 output
__device__ float d_bn2m[NL*NF], d_bn2r[NL*NF];
__device__ float d_y    [NL*512];              // fc3 per-row output

// ---------------- bf16 split-pack helpers ----------------
// pack x ~= hi + lo (both bf16): low16 = hi, high16 = lo.
// 2-pass mma: pass1 A=(hi,lo) x B=(hi,hi) -> hiA*hiB + loA*hiB
//             pass2 A=(hi,hi) x B=(lo,0)  -> hiA*loB   (drops only loA*loB ~2^-18)
__device__ __forceinline__ uint32_t packsplit(float x){
    __nv_bfloat16 h = __float2bfloat16(x);
    float r = x - __bfloat162float(h);
    __nv_bfloat16 l = __float2bfloat16(r);
    return (uint32_t)__bfloat16_as_ushort(h) | ((uint32_t)__bfloat16_as_ushort(l) << 16);
}
__device__ __forceinline__ uint32_t duphi(uint32_t p){ return __byte_perm(p, p, 0x1010); } // (hi,hi)
__device__ __forceinline__ uint32_t lozero(uint32_t p){ return __byte_perm(p, 0, 0x4432); } // (lo,0)

__device__ __forceinline__ void mma_bf16(float* c, const uint32_t* a, const uint32_t* b){
    asm volatile("mma.sync.aligned.m16n8k16.row.col.f32.bf16.bf16.f32 "
        "{%0,%1,%2,%3}, {%4,%5,%6,%7}, {%8,%9}, {%0,%1,%2,%3};"
        : "+f"(c[0]),"+f"(c[1]),"+f"(c[2]),"+f"(c[3])
        : "r"(a[0]),"r"(a[1]),"r"(a[2]),"r"(a[3]), "r"(b[0]),"r"(b[1]));
}

// cp.async helpers (16B)
__device__ __forceinline__ void cpasync16(void* smem_dst, const void* gmem_src){
    uint32_t sa = (uint32_t)__cvta_generic_to_shared(smem_dst);
    asm volatile("cp.async.cg.shared.global [%0], [%1], 16;" :: "r"(sa), "l"(gmem_src));
}
__device__ __forceinline__ void cpasync_commit(){ asm volatile("cp.async.commit_group;"); }
__device__ __forceinline__ void cpasync_wait1(){ asm volatile("cp.async.wait_group 1;"); }
__device__ __forceinline__ void cpasync_wait0(){ asm volatile("cp.async.wait_group 0;"); }

// ---------------- elementwise split-pack ----------------
__global__ void k_split(const float* __restrict__ src, uint32_t* __restrict__ dst, int n){
    int idx = blockIdx.x*256 + threadIdx.x;
    if (idx < n) dst[idx] = packsplit(src[idx]);
}

// ---------------- precompute sigmoid(score_embed) ----------------
__global__ void k_sigse(const float* __restrict__ se){
    int idx = blockIdx.x*256 + threadIdx.x;
    if (idx < NL*NS*NS) d_sigse[idx] = 1.f/(1.f+expf(-se[idx]));
}

// ---------------- fc0 projection (2-pass bf16-split mma, cp.async double-buffered)
// out[i][b][t][e] = sum_d feat[b][i*D+d][t] * w0[i][e][d] + b0[i][e]
// grid (4 e-tiles, B, L), 512 threads (16 warps). CTA: 192 t x 128 e, 16 elems/chunk.
// warp w: mw=w>>2 -> t-base mw*48 (3 m-tiles), nw=w&3 -> e-base nw*32 (4 n-tiles).
#define PAS 200
__global__ void __launch_bounds__(512) k_proj(const uint32_t* __restrict__ featP,
                       const float* __restrict__ b0, uint32_t* __restrict__ outP){
    const int i = blockIdx.z, b = blockIdx.y, e0 = blockIdx.x*128;
    const int tid = threadIdx.x;
    const int w = tid>>5, lane = tid&31;
    const int g = lane>>2, c = lane&3;
    const int mw = w>>2, nw = w&3;
    __shared__ uint32_t As[2][16*PAS];    // [kk][t]   2 x 12800B
    __shared__ uint32_t Bs[2][128*20];    // [e][kk]   2 x 10240B -> 46KB static
    float acc[3][4][4];
#pragma unroll
    for (int mt=0;mt<3;mt++)
#pragma unroll
        for (int nt=0;nt<4;nt++)
#pragma unroll
            for (int r=0;r<4;r++) acc[mt][nt][r]=0.f;
    const uint32_t* fbase = featP + (size_t)(b*(ND*NL) + i*ND)*NS;
    const uint32_t* wbase = d_w0p + (size_t)i*ND*ND + (size_t)e0*ND;
    const int tb = mw*48;

    auto stageFull = [&](int ch, int bufi){
        const int kc = ch*16;
        // As: 16 rows x 48 uint4 = 768 ; Bs: 128 rows x 4 uint4 = 512 ; total 1280
        for (int idx = tid; idx < 1280; idx += 512){
            if (idx < 768){
                int kk = idx / 48, j = idx % 48;
                cpasync16(&As[bufi][kk*PAS + j*4], &fbase[(size_t)(kc+kk)*NS + j*4]);
            } else {
                int r2 = idx - 768;
                int ee = r2 >> 2, j = r2 & 3;
                cpasync16(&Bs[bufi][ee*20 + j*4], &wbase[(size_t)ee*ND + kc + j*4]);
            }
        }
        cpasync_commit();
    };

    stageFull(0, 0);
    const int NCH = ND/16;  // 32
    for (int ch = 0; ch < NCH; ch++){
        if (ch + 1 < NCH){ stageFull(ch+1, (ch+1)&1); cpasync_wait1(); }
        else             { cpasync_wait0(); }
        __syncthreads();
        const uint32_t* Ab = As[ch&1];
        const uint32_t* Bb = Bs[ch&1];
#pragma unroll
        for (int ks=0; ks<2; ks++){
            const int k0 = ks*8;
            uint32_t bdup[4][2], blo0[4][2];
#pragma unroll
            for (int nt=0;nt<4;nt++){
                int e = nw*32 + nt*8 + g;
                uint32_t b0r = Bb[e*20 + k0 + c];
                uint32_t b1r = Bb[e*20 + k0 + 4 + c];
                bdup[nt][0] = duphi(b0r);  bdup[nt][1] = duphi(b1r);
                blo0[nt][0] = lozero(b0r); blo0[nt][1] = lozero(b1r);
            }
#pragma unroll
            for (int mt=0;mt<3;mt++){
                int r = tb + mt*16 + g;
                uint32_t araw[4], adup[4];
                araw[0] = Ab[(k0+c)*PAS + r];
                araw[1] = Ab[(k0+c)*PAS + r + 8];
                araw[2] = Ab[(k0+4+c)*PAS + r];
                araw[3] = Ab[(k0+4+c)*PAS + r + 8];
#pragma unroll
                for (int j=0;j<4;j++) adup[j] = duphi(araw[j]);
#pragma unroll
                for (int nt=0;nt<4;nt++){
                    mma_bf16(acc[mt][nt], araw, bdup[nt]);
                    mma_bf16(acc[mt][nt], adup, blo0[nt]);
                }
            }
        }
        __syncthreads();
    }
    // epilogue: + bias, split-pack, store 2 packed elems as uint2
    uint32_t* obase = outP + (size_t)(i*NB+b)*NS*ND;
#pragma unroll
    for (int nt=0;nt<4;nt++){
        int e = e0 + nw*32 + nt*8 + 2*c;
        float b01 = b0[i*ND + e], b11 = b0[i*ND + e + 1];
#pragma unroll
        for (int mt=0;mt<3;mt++){
            int r = tb + mt*16 + g;
            uint2 v0 = make_uint2(packsplit(acc[mt][nt][0] + b01), packsplit(acc[mt][nt][1] + b11));
            uint2 v1 = make_uint2(packsplit(acc[mt][nt][2] + b01), packsplit(acc[mt][nt][3] + b11));
            *reinterpret_cast<uint2*>(&obase[(size_t)r*ND + e])     = v0;
            *reinterpret_cast<uint2*>(&obase[(size_t)(r+8)*ND + e]) = v1;
        }
    }
}

// ---------------- score GEMM (2-pass bf16-split, cp.async 2-stage, K-chunk 32)  [R14 verified]
// grid (256 qk, L), 512 threads (16 warps). CTA: FULL tile t 192 x s 192.
// warp w: mw=w>>2 -> t-base mw*48 (3 m-tiles), nw=w&3 -> s-base nw*48 (6 n-tiles).
// Both rowmax and colmax complete in-CTA. Dynamic smem: 2 x 2 x 192 x 36 x 4B = 110592 B.
#define STR 36
__global__ void __launch_bounds__(512) k_score(){
    extern __shared__ uint32_t dynsm[];
    const int i = blockIdx.y, qk = blockIdx.x;
    const int q = qk >> 4, k = qk & 15;
    const int tid = threadIdx.x;
    const int w = tid>>5, lane = tid&31;
    const int g = lane>>2, c = lane&3;
    const int mw = w>>2, nw = w&3;
    uint32_t* Asb[2] = { dynsm,            dynsm + NS*STR };
    uint32_t* Bsb[2] = { dynsm + 2*NS*STR, dynsm + 3*NS*STR };
    float acc[3][6][4];
#pragma unroll
    for (int mt=0;mt<3;mt++)
#pragma unroll
        for (int nt=0;nt<6;nt++)
#pragma unroll
            for (int r=0;r<4;r++) acc[mt][nt][r]=0.f;
    const uint32_t* qbase = d_qryp + (size_t)(i*NB+q)*NS*ND;
    const uint32_t* kbase = d_keyp + (size_t)(i*NB+k)*NS*ND;
    const int tb = mw*48, sb = nw*48;

    auto stage = [&](int ch, int bufi){
        const int kc = ch*32;
        // As: 192 rows x 8 uint4 = 1536 ; Bs same ; total 3072
        for (int idx = tid; idx < 3072; idx += 512){
            if (idx < 1536){
                int t = idx >> 3, j = idx & 7;
                cpasync16(&Asb[bufi][t*STR + j*4], &qbase[(size_t)t*ND + kc + j*4]);
            } else {
                int r2 = idx - 1536;
                int s = r2 >> 3, j = r2 & 7;
                cpasync16(&Bsb[bufi][s*STR + j*4], &kbase[(size_t)s*ND + kc + j*4]);
            }
        }
        cpasync_commit();
    };

    stage(0, 0);
    const int NCH = ND/32;  // 16
    for (int ch = 0; ch < NCH; ch++){
        if (ch + 1 < NCH){ stage(ch+1, (ch+1)&1); cpasync_wait1(); }
        else             { cpasync_wait0(); }
        __syncthreads();
        const uint32_t* Ab = Asb[ch&1];
        const uint32_t* Bb = Bsb[ch&1];
#pragma unroll
        for (int ks=0; ks<4; ks++){
            const int k0 = ks*8;
            uint32_t bdup[6][2], blo0[6][2];
#pragma unroll
            for (int nt=0;nt<6;nt++){
                int s = sb + nt*8 + g;
                uint32_t b0r = Bb[s*STR + k0 + c];
                uint32_t b1r = Bb[s*STR + k0 + 4 + c];
                bdup[nt][0] = duphi(b0r);  bdup[nt][1] = duphi(b1r);
                blo0[nt][0] = lozero(b0r); blo0[nt][1] = lozero(b1r);
            }
#pragma unroll
            for (int mt=0;mt<3;mt++){
                int t = tb + mt*16 + g;
                uint32_t araw[4], adup[4];
                araw[0] = Ab[t*STR + k0 + c];
                araw[1] = Ab[(t+8)*STR + k0 + c];
                araw[2] = Ab[t*STR + k0 + 4 + c];
                araw[3] = Ab[(t+8)*STR + k0 + 4 + c];
#pragma unroll
                for (int j=0;j<4;j++) adup[j] = duphi(araw[j]);
#pragma unroll
                for (int nt=0;nt<6;nt++){
                    mma_bf16(acc[mt][nt], araw, bdup[nt]);
                    mma_bf16(acc[mt][nt], adup, blo0[nt]);
                }
            }
        }
        __syncthreads();
    }
    // mask by sigmoid(score_embed): element (row=t, col=s) *= sigse[s*NS + t]
    const float* sbase = d_sigse + (size_t)i*NS*NS;
#pragma unroll
    for (int mt=0;mt<3;mt++){
        int t0v = tb + mt*16 + g, t1v = t0v + 8;
#pragma unroll
        for (int nt=0;nt<6;nt++){
            int sc = sb + nt*8 + 2*c;
            acc[mt][nt][0] *= sbase[(size_t)sc*NS + t0v];
            acc[mt][nt][1] *= sbase[(size_t)(sc+1)*NS + t0v];
            acc[mt][nt][2] *= sbase[(size_t)sc*NS + t1v];
            acc[mt][nt][3] *= sbase[(size_t)(sc+1)*NS + t1v];
        }
    }
    // reduction scratch aliases dynsm (mainloop done; As[1]/Bs untouched)
    float* rowbuf = reinterpret_cast<float*>(dynsm);        // [16][48]
    float* colbuf = rowbuf + 16*48;                          // [16][48]
    // ---- rowmax partial: per warp, max over its 48 s, per t row ----
    float rm[3][2];
#pragma unroll
    for (int mt=0;mt<3;mt++){
        float m0 = fmaxf(acc[mt][0][0], acc[mt][0][1]);
        float m1 = fmaxf(acc[mt][0][2], acc[mt][0][3]);
#pragma unroll
        for (int nt=1;nt<6;nt++){
            m0 = fmaxf(m0, fmaxf(acc[mt][nt][0], acc[mt][nt][1]));
            m1 = fmaxf(m1, fmaxf(acc[mt][nt][2], acc[mt][nt][3]));
        }
        rm[mt][0] = m0; rm[mt][1] = m1;
    }
#pragma unroll
    for (int off=1; off<4; off<<=1)
#pragma unroll
        for (int mt=0;mt<3;mt++){
            rm[mt][0] = fmaxf(rm[mt][0], __shfl_xor_sync(0xffffffffu, rm[mt][0], off));
            rm[mt][1] = fmaxf(rm[mt][1], __shfl_xor_sync(0xffffffffu, rm[mt][1], off));
        }
    if (c == 0){
#pragma unroll
        for (int mt=0;mt<3;mt++){
            rowbuf[w*48 + mt*16 + g]     = rm[mt][0];
            rowbuf[w*48 + mt*16 + g + 8] = rm[mt][1];
        }
    }
    // ---- colmax partial: per warp, max over its 48 t, per s col ----
    float cm[6][2];
#pragma unroll
    for (int nt=0;nt<6;nt++){
        float m0 = fmaxf(acc[0][nt][0], acc[0][nt][2]);
        float m1 = fmaxf(acc[0][nt][1], acc[0][nt][3]);
#pragma unroll
        for (int mt=1;mt<3;mt++){
            m0 = fmaxf(m0, fmaxf(acc[mt][nt][0], acc[mt][nt][2]));
            m1 = fmaxf(m1, fmaxf(acc[mt][nt][1], acc[mt][nt][3]));
        }
        cm[nt][0] = m0; cm[nt][1] = m1;
    }
#pragma unroll
    for (int off=4; off<32; off<<=1)
#pragma unroll
        for (int nt=0;nt<6;nt++){
            cm[nt][0] = fmaxf(cm[nt][0], __shfl_xor_sync(0xffffffffu, cm[nt][0], off));
            cm[nt][1] = fmaxf(cm[nt][1], __shfl_xor_sync(0xffffffffu, cm[nt][1], off));
        }
    if (g == 0){
#pragma unroll
        for (int nt=0;nt<6;nt++){
            colbuf[w*48 + nt*8 + 2*c]     = cm[nt][0];
            colbuf[w*48 + nt*8 + 2*c + 1] = cm[nt][1];
        }
    }
    __syncthreads();
    // final merge: 192 rowmax (over 4 n-warps) + 192 colmax (over 4 m-warps), both direct writes
    for (int idx = tid; idx < 2*NS; idx += 512){
        if (idx < NS){       // rowmax for t row idx: warps w = mw*4 + nw, nw 0..3
            int mwv = idx / 48, j = idx % 48;
            float v = rowbuf[(mwv*4 + 0)*48 + j];
#pragma unroll
            for (int nwv=1; nwv<4; nwv++) v = fmaxf(v, rowbuf[(mwv*4 + nwv)*48 + j]);
            d_x[((size_t)i*512 + 2*qk)*NS + idx] = v;
        } else {             // colmax for s col: warps w = mw*4 + nw, mw 0..3
            int sl = idx - NS;
            int nwv = sl / 48, j = sl % 48;
            float v = colbuf[(0*4 + nwv)*48 + j];
#pragma unroll
            for (int mwv=1; mwv<4; mwv++) v = fmaxf(v, colbuf[(mwv*4 + nwv)*48 + j]);
            d_x[((size_t)i*512 + 2*qk + 1)*NS + sl] = v;
        }
    }
}

// ---------------- bn1 stats (whole-tensor mean/var per layer), double accum
__global__ void k_bn1(){
    const int i = blockIdx.x, tid = threadIdx.x;   // 8 blocks x 512 threads
    const float* p = d_x + (size_t)i*512*NS;
    double s=0.0, sq=0.0;
    for (int idx=tid; idx<512*NS; idx+=512){ double v = p[idx]; s+=v; sq+=v*v; }
    __shared__ double ss[512], sqs[512];
    ss[tid]=s; sqs[tid]=sq; __syncthreads();
    for (int off=256; off; off>>=1){
        if (tid<off){ ss[tid]+=ss[tid+off]; sqs[tid]+=sqs[tid+off]; }
        __syncthreads();
    }
    if (tid==0){
        double n = 512.0*NS;
        double mean = ss[0]/n;
        double var  = sqs[0]/n - mean*mean;
        d_bn1m[i] = (float)mean;
        d_bn1r[i] = (float)rsqrt(var + 1e-5);
    }
}

// ---------------- fc2: u = bn1(x) @ w2^T + b2.  grid (32 f-tiles, 8 r-tiles, L), 256 thr, CTA 64x64.
__global__ void k_fc2(const float* __restrict__ w2, const float* __restrict__ b2,
                      const float* __restrict__ g1, const float* __restrict__ b1){
    const int i = blockIdx.z, r0 = blockIdx.y*64, f0 = blockIdx.x*64;
    const int tid = threadIdx.x, tx = tid&15, ty = tid>>4;
    const float alpha = g1[i]*d_bn1r[i];
    const float beta  = b1[i] - d_bn1m[i]*alpha;
    __shared__ float Xs[64][33], Ws[64][33];
    float acc[4][4];
#pragma unroll
    for (int u=0;u<4;u++)
#pragma unroll
        for (int v=0;v<4;v++) acc[u][v]=0.f;
    const float* xbase = d_x + (size_t)(i*512 + r0)*NS;
    const float* wbase = w2  + (size_t)(i*NF + f0)*NS;
    for (int kc=0; kc<NS; kc+=32){
        for (int idx=tid; idx<64*32; idx+=256){
            int rr = idx>>5, kk = idx&31;
            Xs[rr][kk] = xbase[(size_t)rr*NS + kc+kk]*alpha + beta;
        }
        for (int idx=tid; idx<64*32; idx+=256){
            int ff = idx>>5, kk = idx&31;
            Ws[ff][kk] = wbase[(size_t)ff*NS + kc+kk];
        }
        __syncthreads();
#pragma unroll
        for (int kk=0; kk<32; kk++){
            float a[4], bb[4];
#pragma unroll
            for (int u=0;u<4;u++) a[u]  = Xs[ty*4+u][kk];
#pragma unroll
            for (int v=0;v<4;v++) bb[v] = Ws[tx*4+v][kk];
#pragma unroll
            for (int u=0;u<4;u++)
#pragma unroll
                for (int v=0;v<4;v++) acc[u][v] = fmaf(a[u], bb[v], acc[u][v]);
        }
        __syncthreads();
    }
#pragma unroll
    for (int u=0;u<4;u++){
        int r = r0 + ty*4 + u;
#pragma unroll
        for (int v=0;v<4;v++){
            int f = f0 + tx*4 + v;
            d_u[(size_t)(i*512 + r)*NF + f] = acc[u][v] + b2[i*NF + f];
        }
    }
}

// ---------------- bn2 stats (per-feature mean/var over 512 rows)
__global__ void k_bn2(){
    const int i = blockIdx.y, f0 = blockIdx.x*64;
    const int tid = threadIdx.x, fx = tid&63, rg = tid>>6;
    const float* p = d_u + (size_t)i*512*NF + f0 + fx;
    float s=0.f, sq=0.f;
    for (int r=rg; r<512; r+=4){ float v = p[(size_t)r*NF]; s+=v; sq+=v*v; }
    __shared__ float ss[256], sqs[256];
    ss[tid]=s; sqs[tid]=sq; __syncthreads();
    if (rg==0){
        float S  = ss[fx]  + ss[fx+64]  + ss[fx+128]  + ss[fx+192];
        float SQ = sqs[fx] + sqs[fx+64] + sqs[fx+128] + sqs[fx+192];
        float mean = S/512.f;
        float var  = SQ/512.f - mean*mean;
        d_bn2m[i*NF+f0+fx] = mean;
        d_bn2r[i*NF+f0+fx] = rsqrtf(var + EPSF);
    }
}

// ---------------- fc3: y[row] = relu(bn2(u[row])) . w3   (one warp per row)
__global__ void k_fc3(const float* __restrict__ g2, const float* __restrict__ bb2,
                      const float* __restrict__ w3){
    const int row  = blockIdx.x*8 + (threadIdx.x>>5);   // 512 blocks x 8 warps = 4096 rows
    const int lane = threadIdx.x & 31;
    const int i = row >> 9;
    const float* up = d_u + (size_t)row*NF;
    float s = 0.f;
    for (int f=lane; f<NF; f+=32){
        int gi = i*NF + f;
        float z = g2[gi]*(up[f]-d_bn2m[gi])*d_bn2r[gi] + bb2[gi];
        z = fmaxf(z, 0.f);
        s = fmaf(z, w3[gi], s);
    }
#pragma unroll
    for (int off=16; off; off>>=1) s += __shfl_xor_sync(0xffffffffu, s, off);
    if (lane==0) d_y[row] = s;
}

// ---------------- final: pair-sum, bn3 per layer, accumulate, labels
__global__ void k_final(const float* __restrict__ b3, const float* __restrict__ g3,
                        const float* __restrict__ bb3, const int* __restrict__ targets,
                        float* __restrict__ out, int out_size){
    const int qk = threadIdx.x;   // 256
    __shared__ double ss[256], sqs[256];
    float accum = 0.f;
    for (int i=0;i<NL;i++){
        float p = d_y[i*512 + 2*qk] + d_y[i*512 + 2*qk + 1] + 2.f*b3[i];
        ss[qk] = (double)p; sqs[qk] = (double)p*(double)p;
        __syncthreads();
        for (int off=128; off; off>>=1){
            if (qk<off){ ss[qk]+=ss[qk+off]; sqs[qk]+=sqs[qk+off]; }
            __syncthreads();
        }
        double mean = ss[0]/256.0;
        double var  = sqs[0]/256.0 - mean*mean;
        float rstd  = (float)rsqrt(var + 1e-5);
        accum += g3[i]*((p - (float)mean)*rstd) + bb3[i];
        __syncthreads();   // protect ss/sqs before next layer overwrites
    }
    out[qk] = accum;
    if (out_size >= 512){
        int qq = qk >> 4, kk = qk & 15;
        out[256 + qk] = (targets[qq]==targets[kk]) ? 1.f : 0.f;
    }
}

// ---------------- launcher ----------------
extern "C" void kernel_launch(void* const* d_in, const int* in_sizes, int n_in,
                              void* d_out, int out_size){
    const float* q_feat = (const float*)d_in[0];
    const float* g_feat = (const float*)d_in[1];
    const int*   targets= (const int*)  d_in[2];
    const float* se     = (const float*)d_in[3];
    const float* fc0w   = (const float*)d_in[4];
    const float* fc0b   = (const float*)d_in[5];
    const float* bn1g   = (const float*)d_in[6];
    const float* bn1b   = (const float*)d_in[7];
    const float* fc2w   = (const float*)d_in[8];
    const float* fc2b   = (const float*)d_in[9];
    const float* bn2g   = (const float*)d_in[10];
    const float* bn2b   = (const float*)d_in[11];
    const float* fc3w   = (const float*)d_in[12];
    const float* fc3b   = (const float*)d_in[13];
    const float* bn3g   = (const float*)d_in[14];
    const float* bn3b   = (const float*)d_in[15];
    float* out = (float*)d_out;

    uint32_t *p_qfp, *p_gfp, *p_w0p, *p_qryp, *p_keyp;
    cudaGetSymbolAddress((void**)&p_qfp,  d_qfp);
    cudaGetSymbolAddress((void**)&p_gfp,  d_gfp);
    cudaGetSymbolAddress((void**)&p_w0p,  d_w0p);
    cudaGetSymbolAddress((void**)&p_qryp, d_qryp);
    cudaGetSymbolAddress((void**)&p_keyp, d_keyp);

    const int nfeat = NB*NL*ND*NS;
    const int nw0   = NL*ND*ND;
    const int SCORE_SMEM = 4*NS*STR*4;   // 110592 B (2-stage, R14 verified)

    // context op (not stream-ordered, not captured, no allocation) — idempotent
    cudaFuncSetAttribute(k_score, cudaFuncAttributeMaxDynamicSharedMemorySize, SCORE_SMEM);

    k_sigse<<<(NL*NS*NS+255)/256, 256>>>(se);
    k_split<<<(nfeat+255)/256, 256>>>(q_feat, p_qfp, nfeat);
    k_split<<<(nfeat+255)/256, 256>>>(g_feat, p_gfp, nfeat);
    k_split<<<(nw0+255)/256,   256>>>(fc0w,   p_w0p, nw0);
    k_proj<<<dim3(4, NB, NL), 512>>>(p_qfp, fc0b, p_qryp);
    k_proj<<<dim3(4, NB, NL), 512>>>(p_gfp, fc0b, p_keyp);
    k_score<<<dim3(256, NL), 512, SCORE_SMEM>>>();
    k_bn1<<<NL, 512>>>();
    k_fc2<<<dim3(32, 8, NL), 256>>>(fc2w, fc2b, bn1g, bn1b);
    k_bn2<<<dim3(32, NL), 256>>>();
    k_fc3<<<512, 256>>>(bn2g, bn2b, fc3w);
    k_final<<<1, 256>>>(fc3b, bn3g, bn3b, targets, out, out_size);
}

// round 17
// speedup vs baseline: 1.5857x; 1.0465x over previous
#include <cuda_runtime.h>
#include <cuda_bf16.h>
#include <math.h>
#include <stdint.h>

#define NL 8
#define NS 192
#define ND 512
#define NF 2048
#define NB 16
#define EPSF 1e-5f

// ---------------- scratch (static device globals; no allocations) ----------------
__device__ uint32_t d_qfp  [NB*NL*ND*NS];      // packed bf16(hi,lo) q_feat  [b][i*D+d][t]
__device__ uint32_t d_gfp  [NB*NL*ND*NS];      // packed g_feat
__device__ uint32_t d_w0p  [NL*ND*ND];         // packed fc0_w   [i][e][d]
__device__ uint32_t d_qryp [NL*NB*NS*ND];      // packed query   [i][b][t][e]
__device__ uint32_t d_keyp [NL*NB*NS*ND];      // packed key     [i][b][s][e]
__device__ float d_sigse[NL*NS*NS];            // sigmoid(score_embed)
__device__ float d_x    [NL*512*NS];           // [i][r=2qk+branch][S]
__device__ float d_bn1m[NL], d_bn1r[NL];
__device__ float d_u    [NL*512*NF];           // fc2 output
__device__ float d_bn2m[NL*NF], d_bn2r[NL*NF];
__device__ float d_y    [NL*512];              // fc3 per-row output

// ---------------- bf16 split-pack helpers ----------------
// pack x ~= hi + lo (both bf16): low16 = hi, high16 = lo.
// 2-pass mma: pass1 A=(hi,lo) x B=(hi,hi) -> hiA*hiB + loA*hiB
//             pass2 A=(hi,hi) x B=(lo,0)  -> hiA*loB   (drops only loA*loB ~2^-18)
__device__ __forceinline__ uint32_t packsplit(float x){
    __nv_bfloat16 h = __float2bfloat16(x);
    float r = x - __bfloat162float(h);
    __nv_bfloat16 l = __float2bfloat16(r);
    return (uint32_t)__bfloat16_as_ushort(h) | ((uint32_t)__bfloat16_as_ushort(l) << 16);
}
__device__ __forceinline__ uint32_t duphi(uint32_t p){ return __byte_perm(p, p, 0x1010); } // (hi,hi)
__device__ __forceinline__ uint32_t lozero(uint32_t p){ return __byte_perm(p, 0, 0x4432); } // (lo,0)

__device__ __forceinline__ void mma_bf16(float* c, const uint32_t* a, const uint32_t* b){
    asm volatile("mma.sync.aligned.m16n8k16.row.col.f32.bf16.bf16.f32 "
        "{%0,%1,%2,%3}, {%4,%5,%6,%7}, {%8,%9}, {%0,%1,%2,%3};"
        : "+f"(c[0]),"+f"(c[1]),"+f"(c[2]),"+f"(c[3])
        : "r"(a[0]),"r"(a[1]),"r"(a[2]),"r"(a[3]), "r"(b[0]),"r"(b[1]));
}

// cp.async helpers (16B)
__device__ __forceinline__ void cpasync16(void* smem_dst, const void* gmem_src){
    uint32_t sa = (uint32_t)__cvta_generic_to_shared(smem_dst);
    asm volatile("cp.async.cg.shared.global [%0], [%1], 16;" :: "r"(sa), "l"(gmem_src));
}
__device__ __forceinline__ void cpasync_commit(){ asm volatile("cp.async.commit_group;"); }
__device__ __forceinline__ void cpasync_wait1(){ asm volatile("cp.async.wait_group 1;"); }
__device__ __forceinline__ void cpasync_wait0(){ asm volatile("cp.async.wait_group 0;"); }

// ---------------- merged elementwise split-pack (q_feat + g_feat + w0 in one grid)
__global__ void k_splitall(const float* __restrict__ qf, const float* __restrict__ gf,
                           const float* __restrict__ w0, int nfeat, int nw0){
    int idx = blockIdx.x*256 + threadIdx.x;
    if (idx < nfeat)              d_qfp[idx]         = packsplit(qf[idx]);
    else if (idx < 2*nfeat)       d_gfp[idx - nfeat] = packsplit(gf[idx - nfeat]);
    else if (idx < 2*nfeat + nw0) d_w0p[idx - 2*nfeat] = packsplit(w0[idx - 2*nfeat]);
}

// ---------------- precompute sigmoid(score_embed) ----------------
__global__ void k_sigse(const float* __restrict__ se){
    int idx = blockIdx.x*256 + threadIdx.x;
    if (idx < NL*NS*NS) d_sigse[idx] = 1.f/(1.f+expf(-se[idx]));
}

// ---------------- fc0 projection (2-pass bf16-split mma, cp.async double-buffered)
// [R14 verified math] grid (8 e-tiles, 2*NB, L), 256 threads. CTA: 192 t x 64 e.
// blockIdx.y: b = y&15 selects batch; sel = y>>4 selects (q_feat->query) vs (g_feat->key).
#define PAS 200
__global__ void __launch_bounds__(256) k_proj(const float* __restrict__ b0){
    const int i = blockIdx.z, by = blockIdx.y, e0 = blockIdx.x*64;
    const int b = by & 15, sel = by >> 4;
    const uint32_t* featP = sel ? d_gfp : d_qfp;
    uint32_t*       outP  = sel ? d_keyp : d_qryp;
    const int tid = threadIdx.x;
    const int w = tid>>5, lane = tid&31;
    const int g = lane>>2, c = lane&3;
    const int mw = w>>1, nw = w&1;
    __shared__ uint32_t As[2][16*PAS];   // [kk][t]
    __shared__ uint32_t Bs[2][64*20];    // [e][kk]
    float acc[3][4][4];
#pragma unroll
    for (int mt=0;mt<3;mt++)
#pragma unroll
        for (int nt=0;nt<4;nt++)
#pragma unroll
            for (int r=0;r<4;r++) acc[mt][nt][r]=0.f;
    const uint32_t* fbase = featP + (size_t)(b*(ND*NL) + i*ND)*NS;
    const uint32_t* wbase = d_w0p + (size_t)i*ND*ND + (size_t)e0*ND;
    const int tb = mw*48;

    auto stageFull = [&](int ch, int bufi){
        const int kc = ch*16;
        // As: 16 rows x 48 uint4 = 768 ; Bs: 64 rows x 4 uint4 = 256 ; total 1024
        for (int idx = tid; idx < 1024; idx += 256){
            if (idx < 768){
                int kk = idx / 48, j = idx % 48;
                cpasync16(&As[bufi][kk*PAS + j*4], &fbase[(size_t)(kc+kk)*NS + j*4]);
            } else {
                int r2 = idx - 768;
                int ee = r2 >> 2, j = r2 & 3;
                cpasync16(&Bs[bufi][ee*20 + j*4], &wbase[(size_t)ee*ND + kc + j*4]);
            }
        }
        cpasync_commit();
    };

    stageFull(0, 0);
    const int NCH = ND/16;  // 32
    for (int ch = 0; ch < NCH; ch++){
        if (ch + 1 < NCH){ stageFull(ch+1, (ch+1)&1); cpasync_wait1(); }
        else             { cpasync_wait0(); }
        __syncthreads();
        const uint32_t* Ab = As[ch&1];
        const uint32_t* Bb = Bs[ch&1];
#pragma unroll
        for (int ks=0; ks<2; ks++){
            const int k0 = ks*8;
            uint32_t bdup[4][2], blo0[4][2];
#pragma unroll
            for (int nt=0;nt<4;nt++){
                int e = nw*32 + nt*8 + g;
                uint32_t b0r = Bb[e*20 + k0 + c];
                uint32_t b1r = Bb[e*20 + k0 + 4 + c];
                bdup[nt][0] = duphi(b0r);  bdup[nt][1] = duphi(b1r);
                blo0[nt][0] = lozero(b0r); blo0[nt][1] = lozero(b1r);
            }
#pragma unroll
            for (int mt=0;mt<3;mt++){
                int r = tb + mt*16 + g;
                uint32_t araw[4], adup[4];
                araw[0] = Ab[(k0+c)*PAS + r];
                araw[1] = Ab[(k0+c)*PAS + r + 8];
                araw[2] = Ab[(k0+4+c)*PAS + r];
                araw[3] = Ab[(k0+4+c)*PAS + r + 8];
#pragma unroll
                for (int j=0;j<4;j++) adup[j] = duphi(araw[j]);
#pragma unroll
                for (int nt=0;nt<4;nt++){
                    mma_bf16(acc[mt][nt], araw, bdup[nt]);
                    mma_bf16(acc[mt][nt], adup, blo0[nt]);
                }
            }
        }
        __syncthreads();
    }
    // epilogue: + bias, split-pack, store 2 packed elems as uint2
    uint32_t* obase = outP + (size_t)(i*NB+b)*NS*ND;
#pragma unroll
    for (int nt=0;nt<4;nt++){
        int e = e0 + nw*32 + nt*8 + 2*c;
        float b01 = b0[i*ND + e], b11 = b0[i*ND + e + 1];
#pragma unroll
        for (int mt=0;mt<3;mt++){
            int r = tb + mt*16 + g;
            uint2 v0 = make_uint2(packsplit(acc[mt][nt][0] + b01), packsplit(acc[mt][nt][1] + b11));
            uint2 v1 = make_uint2(packsplit(acc[mt][nt][2] + b01), packsplit(acc[mt][nt][3] + b11));
            *reinterpret_cast<uint2*>(&obase[(size_t)r*ND + e])     = v0;
            *reinterpret_cast<uint2*>(&obase[(size_t)(r+8)*ND + e]) = v1;
        }
    }
}

// ---------------- score GEMM (2-pass bf16-split, cp.async 2-stage, K-chunk 32)  [R14 verified]
// grid (256 qk, L), 512 threads (16 warps). CTA: FULL tile t 192 x s 192.
// warp w: mw=w>>2 -> t-base mw*48 (3 m-tiles), nw=w&3 -> s-base nw*48 (6 n-tiles).
// Both rowmax and colmax complete in-CTA. Dynamic smem: 2 x 2 x 192 x 36 x 4B = 110592 B.
#define STR 36
__global__ void __launch_bounds__(512) k_score(){
    extern __shared__ uint32_t dynsm[];
    const int i = blockIdx.y, qk = blockIdx.x;
    const int q = qk >> 4, k = qk & 15;
    const int tid = threadIdx.x;
    const int w = tid>>5, lane = tid&31;
    const int g = lane>>2, c = lane&3;
    const int mw = w>>2, nw = w&3;
    uint32_t* Asb[2] = { dynsm,            dynsm + NS*STR };
    uint32_t* Bsb[2] = { dynsm + 2*NS*STR, dynsm + 3*NS*STR };
    float acc[3][6][4];
#pragma unroll
    for (int mt=0;mt<3;mt++)
#pragma unroll
        for (int nt=0;nt<6;nt++)
#pragma unroll
            for (int r=0;r<4;r++) acc[mt][nt][r]=0.f;
    const uint32_t* qbase = d_qryp + (size_t)(i*NB+q)*NS*ND;
    const uint32_t* kbase = d_keyp + (size_t)(i*NB+k)*NS*ND;
    const int tb = mw*48, sb = nw*48;

    auto stage = [&](int ch, int bufi){
        const int kc = ch*32;
        // As: 192 rows x 8 uint4 = 1536 ; Bs same ; total 3072
        for (int idx = tid; idx < 3072; idx += 512){
            if (idx < 1536){
                int t = idx >> 3, j = idx & 7;
                cpasync16(&Asb[bufi][t*STR + j*4], &qbase[(size_t)t*ND + kc + j*4]);
            } else {
                int r2 = idx - 1536;
                int s = r2 >> 3, j = r2 & 7;
                cpasync16(&Bsb[bufi][s*STR + j*4], &kbase[(size_t)s*ND + kc + j*4]);
            }
        }
        cpasync_commit();
    };

    stage(0, 0);
    const int NCH = ND/32;  // 16
    for (int ch = 0; ch < NCH; ch++){
        if (ch + 1 < NCH){ stage(ch+1, (ch+1)&1); cpasync_wait1(); }
        else             { cpasync_wait0(); }
        __syncthreads();
        const uint32_t* Ab = Asb[ch&1];
        const uint32_t* Bb = Bsb[ch&1];
#pragma unroll
        for (int ks=0; ks<4; ks++){
            const int k0 = ks*8;
            uint32_t bdup[6][2], blo0[6][2];
#pragma unroll
            for (int nt=0;nt<6;nt++){
                int s = sb + nt*8 + g;
                uint32_t b0r = Bb[s*STR + k0 + c];
                uint32_t b1r = Bb[s*STR + k0 + 4 + c];
                bdup[nt][0] = duphi(b0r);  bdup[nt][1] = duphi(b1r);
                blo0[nt][0] = lozero(b0r); blo0[nt][1] = lozero(b1r);
            }
#pragma unroll
            for (int mt=0;mt<3;mt++){
                int t = tb + mt*16 + g;
                uint32_t araw[4], adup[4];
                araw[0] = Ab[t*STR + k0 + c];
                araw[1] = Ab[(t+8)*STR + k0 + c];
                araw[2] = Ab[t*STR + k0 + 4 + c];
                araw[3] = Ab[(t+8)*STR + k0 + 4 + c];
#pragma unroll
                for (int j=0;j<4;j++) adup[j] = duphi(araw[j]);
#pragma unroll
                for (int nt=0;nt<6;nt++){
                    mma_bf16(acc[mt][nt], araw, bdup[nt]);
                    mma_bf16(acc[mt][nt], adup, blo0[nt]);
                }
            }
        }
        __syncthreads();
    }
    // mask by sigmoid(score_embed): element (row=t, col=s) *= sigse[s*NS + t]
    const float* sbase = d_sigse + (size_t)i*NS*NS;
#pragma unroll
    for (int mt=0;mt<3;mt++){
        int t0v = tb + mt*16 + g, t1v = t0v + 8;
#pragma unroll
        for (int nt=0;nt<6;nt++){
            int sc = sb + nt*8 + 2*c;
            acc[mt][nt][0] *= sbase[(size_t)sc*NS + t0v];
            acc[mt][nt][1] *= sbase[(size_t)(sc+1)*NS + t0v];
            acc[mt][nt][2] *= sbase[(size_t)sc*NS + t1v];
            acc[mt][nt][3] *= sbase[(size_t)(sc+1)*NS + t1v];
        }
    }
    // reduction scratch aliases dynsm (mainloop done; As[1]/Bs untouched)
    float* rowbuf = reinterpret_cast<float*>(dynsm);        // [16][48]
    float* colbuf = rowbuf + 16*48;                          // [16][48]
    // ---- rowmax partial: per warp, max over its 48 s, per t row ----
    float rm[3][2];
#pragma unroll
    for (int mt=0;mt<3;mt++){
        float m0 = fmaxf(acc[mt][0][0], acc[mt][0][1]);
        float m1 = fmaxf(acc[mt][0][2], acc[mt][0][3]);
#pragma unroll
        for (int nt=1;nt<6;nt++){
            m0 = fmaxf(m0, fmaxf(acc[mt][nt][0], acc[mt][nt][1]));
            m1 = fmaxf(m1, fmaxf(acc[mt][nt][2], acc[mt][nt][3]));
        }
        rm[mt][0] = m0; rm[mt][1] = m1;
    }
#pragma unroll
    for (int off=1; off<4; off<<=1)
#pragma unroll
        for (int mt=0;mt<3;mt++){
            rm[mt][0] = fmaxf(rm[mt][0], __shfl_xor_sync(0xffffffffu, rm[mt][0], off));
            rm[mt][1] = fmaxf(rm[mt][1], __shfl_xor_sync(0xffffffffu, rm[mt][1], off));
        }
    if (c == 0){
#pragma unroll
        for (int mt=0;mt<3;mt++){
            rowbuf[w*48 + mt*16 + g]     = rm[mt][0];
            rowbuf[w*48 + mt*16 + g + 8] = rm[mt][1];
        }
    }
    // ---- colmax partial: per warp, max over its 48 t, per s col ----
    float cm[6][2];
#pragma unroll
    for (int nt=0;nt<6;nt++){
        float m0 = fmaxf(acc[0][nt][0], acc[0][nt][2]);
        float m1 = fmaxf(acc[0][nt][1], acc[0][nt][3]);
#pragma unroll
        for (int mt=1;mt<3;mt++){
            m0 = fmaxf(m0, fmaxf(acc[mt][nt][0], acc[mt][nt][2]));
            m1 = fmaxf(m1, fmaxf(acc[mt][nt][1], acc[mt][nt][3]));
        }
        cm[nt][0] = m0; cm[nt][1] = m1;
    }
#pragma unroll
    for (int off=4; off<32; off<<=1)
#pragma unroll
        for (int nt=0;nt<6;nt++){
            cm[nt][0] = fmaxf(cm[nt][0], __shfl_xor_sync(0xffffffffu, cm[nt][0], off));
            cm[nt][1] = fmaxf(cm[nt][1], __shfl_xor_sync(0xffffffffu, cm[nt][1], off));
        }
    if (g == 0){
#pragma unroll
        for (int nt=0;nt<6;nt++){
            colbuf[w*48 + nt*8 + 2*c]     = cm[nt][0];
            colbuf[w*48 + nt*8 + 2*c + 1] = cm[nt][1];
        }
    }
    __syncthreads();
    // final merge: 192 rowmax (over 4 n-warps) + 192 colmax (over 4 m-warps), both direct writes
    for (int idx = tid; idx < 2*NS; idx += 512){
        if (idx < NS){       // rowmax for t row idx: warps w = mw*4 + nw, nw 0..3
            int mwv = idx / 48, j = idx % 48;
            float v = rowbuf[(mwv*4 + 0)*48 + j];
#pragma unroll
            for (int nwv=1; nwv<4; nwv++) v = fmaxf(v, rowbuf[(mwv*4 + nwv)*48 + j]);
            d_x[((size_t)i*512 + 2*qk)*NS + idx] = v;
        } else {             // colmax for s col: warps w = mw*4 + nw, mw 0..3
            int sl = idx - NS;
            int nwv = sl / 48, j = sl % 48;
            float v = colbuf[(0*4 + nwv)*48 + j];
#pragma unroll
            for (int mwv=1; mwv<4; mwv++) v = fmaxf(v, colbuf[(mwv*4 + nwv)*48 + j]);
            d_x[((size_t)i*512 + 2*qk + 1)*NS + sl] = v;
        }
    }
}

// ---------------- bn1 stats (whole-tensor mean/var per layer), double accum
__global__ void k_bn1(){
    const int i = blockIdx.x, tid = threadIdx.x;   // 8 blocks x 512 threads
    const float* p = d_x + (size_t)i*512*NS;
    double s=0.0, sq=0.0;
    for (int idx=tid; idx<512*NS; idx+=512){ double v = p[idx]; s+=v; sq+=v*v; }
    __shared__ double ss[512], sqs[512];
    ss[tid]=s; sqs[tid]=sq; __syncthreads();
    for (int off=256; off; off>>=1){
        if (tid<off){ ss[tid]+=ss[tid+off]; sqs[tid]+=sqs[tid+off]; }
        __syncthreads();
    }
    if (tid==0){
        double n = 512.0*NS;
        double mean = ss[0]/n;
        double var  = sqs[0]/n - mean*mean;
        d_bn1m[i] = (float)mean;
        d_bn1r[i] = (float)rsqrt(var + 1e-5);
    }
}

// ---------------- fc2: u = bn1(x) @ w2^T + b2.  grid (32 f-tiles, 8 r-tiles, L), 256 thr, CTA 64x64.
__global__ void k_fc2(const float* __restrict__ w2, const float* __restrict__ b2,
                      const float* __restrict__ g1, const float* __restrict__ b1){
    const int i = blockIdx.z, r0 = blockIdx.y*64, f0 = blockIdx.x*64;
    const int tid = threadIdx.x, tx = tid&15, ty = tid>>4;
    const float alpha = g1[i]*d_bn1r[i];
    const float beta  = b1[i] - d_bn1m[i]*alpha;
    __shared__ float Xs[64][33], Ws[64][33];
    float acc[4][4];
#pragma unroll
    for (int u=0;u<4;u++)
#pragma unroll
        for (int v=0;v<4;v++) acc[u][v]=0.f;
    const float* xbase = d_x + (size_t)(i*512 + r0)*NS;
    const float* wbase = w2  + (size_t)(i*NF + f0)*NS;
    for (int kc=0; kc<NS; kc+=32){
        for (int idx=tid; idx<64*32; idx+=256){
            int rr = idx>>5, kk = idx&31;
            Xs[rr][kk] = xbase[(size_t)rr*NS + kc+kk]*alpha + beta;
        }
        for (int idx=tid; idx<64*32; idx+=256){
            int ff = idx>>5, kk = idx&31;
            Ws[ff][kk] = wbase[(size_t)ff*NS + kc+kk];
        }
        __syncthreads();
#pragma unroll
        for (int kk=0; kk<32; kk++){
            float a[4], bb[4];
#pragma unroll
            for (int u=0;u<4;u++) a[u]  = Xs[ty*4+u][kk];
#pragma unroll
            for (int v=0;v<4;v++) bb[v] = Ws[tx*4+v][kk];
#pragma unroll
            for (int u=0;u<4;u++)
#pragma unroll
                for (int v=0;v<4;v++) acc[u][v] = fmaf(a[u], bb[v], acc[u][v]);
        }
        __syncthreads();
    }
#pragma unroll
    for (int u=0;u<4;u++){
        int r = r0 + ty*4 + u;
#pragma unroll
        for (int v=0;v<4;v++){
            int f = f0 + tx*4 + v;
            d_u[(size_t)(i*512 + r)*NF + f] = acc[u][v] + b2[i*NF + f];
        }
    }
}

// ---------------- bn2 stats (per-feature mean/var over 512 rows)
__global__ void k_bn2(){
    const int i = blockIdx.y, f0 = blockIdx.x*64;
    const int tid = threadIdx.x, fx = tid&63, rg = tid>>6;
    const float* p = d_u + (size_t)i*512*NF + f0 + fx;
    float s=0.f, sq=0.f;
    for (int r=rg; r<512; r+=4){ float v = p[(size_t)r*NF]; s+=v; sq+=v*v; }
    __shared__ float ss[256], sqs[256];
    ss[tid]=s; sqs[tid]=sq; __syncthreads();
    if (rg==0){
        float S  = ss[fx]  + ss[fx+64]  + ss[fx+128]  + ss[fx+192];
        float SQ = sqs[fx] + sqs[fx+64] + sqs[fx+128] + sqs[fx+192];
        float mean = S/512.f;
        float var  = SQ/512.f - mean*mean;
        d_bn2m[i*NF+f0+fx] = mean;
        d_bn2r[i*NF+f0+fx] = rsqrtf(var + EPSF);
    }
}

// ---------------- fc3: y[row] = relu(bn2(u[row])) . w3   (one warp per row)
__global__ void k_fc3(const float* __restrict__ g2, const float* __restrict__ bb2,
                      const float* __restrict__ w3){
    const int row  = blockIdx.x*8 + (threadIdx.x>>5);   // 512 blocks x 8 warps = 4096 rows
    const int lane = threadIdx.x & 31;
    const int i = row >> 9;
    const float* up = d_u + (size_t)row*NF;
    float s = 0.f;
    for (int f=lane; f<NF; f+=32){
        int gi = i*NF + f;
        float z = g2[gi]*(up[f]-d_bn2m[gi])*d_bn2r[gi] + bb2[gi];
        z = fmaxf(z, 0.f);
        s = fmaf(z, w3[gi], s);
    }
#pragma unroll
    for (int off=16; off; off>>=1) s += __shfl_xor_sync(0xffffffffu, s, off);
    if (lane==0) d_y[row] = s;
}

// ---------------- final: pair-sum, bn3 per layer, accumulate, labels
__global__ void k_final(const float* __restrict__ b3, const float* __restrict__ g3,
                        const float* __restrict__ bb3, const int* __restrict__ targets,
                        float* __restrict__ out, int out_size){
    const int qk = threadIdx.x;   // 256
    __shared__ double ss[256], sqs[256];
    float accum = 0.f;
    for (int i=0;i<NL;i++){
        float p = d_y[i*512 + 2*qk] + d_y[i*512 + 2*qk + 1] + 2.f*b3[i];
        ss[qk] = (double)p; sqs[qk] = (double)p*(double)p;
        __syncthreads();
        for (int off=128; off; off>>=1){
            if (qk<off){ ss[qk]+=ss[qk+off]; sqs[qk]+=sqs[qk+off]; }
            __syncthreads();
        }
        double mean = ss[0]/256.0;
        double var  = sqs[0]/256.0 - mean*mean;
        float rstd  = (float)rsqrt(var + 1e-5);
        accum += g3[i]*((p - (float)mean)*rstd) + bb3[i];
        __syncthreads();   // protect ss/sqs before next layer overwrites
    }
    out[qk] = accum;
    if (out_size >= 512){
        int qq = qk >> 4, kk = qk & 15;
        out[256 + qk] = (targets[qq]==targets[kk]) ? 1.f : 0.f;
    }
}

// ---------------- launcher ----------------
extern "C" void kernel_launch(void* const* d_in, const int* in_sizes, int n_in,
                              void* d_out, int out_size){
    const float* q_feat = (const float*)d_in[0];
    const float* g_feat = (const float*)d_in[1];
    const int*   targets= (const int*)  d_in[2];
    const float* se     = (const float*)d_in[3];
    const float* fc0w   = (const float*)d_in[4];
    const float* fc0b   = (const float*)d_in[5];
    const float* bn1g   = (const float*)d_in[6];
    const float* bn1b   = (const float*)d_in[7];
    const float* fc2w   = (const float*)d_in[8];
    const float* fc2b   = (const float*)d_in[9];
    const float* bn2g   = (const float*)d_in[10];
    const float* bn2b   = (const float*)d_in[11];
    const float* fc3w   = (const float*)d_in[12];
    const float* fc3b   = (const float*)d_in[13];
    const float* bn3g   = (const float*)d_in[14];
    const float* bn3b   = (const float*)d_in[15];
    float* out = (float*)d_out;

    const int nfeat = NB*NL*ND*NS;
    const int nw0   = NL*ND*ND;
    const int nsplit = 2*nfeat + nw0;
    const int SCORE_SMEM = 4*NS*STR*4;   // 110592 B (2-stage, R14 verified)

    // context op (not stream-ordered, not captured, no allocation) — idempotent
    cudaFuncSetAttribute(k_score, cudaFuncAttributeMaxDynamicSharedMemorySize, SCORE_SMEM);

    k_sigse<<<(NL*NS*NS+255)/256, 256>>>(se);
    k_splitall<<<(nsplit+255)/256, 256>>>(q_feat, g_feat, fc0w, nfeat, nw0);
    k_proj<<<dim3(8, 2*NB, NL), 256>>>(fc0b);
    k_score<<<dim3(256, NL), 512, SCORE_SMEM>>>();
    k_bn1<<<NL, 512>>>();
    k_fc2<<<dim3(32, 8, NL), 256>>>(fc2w, fc2b, bn1g, bn1b);
    k_bn2<<<dim3(32, NL), 256>>>();
    k_fc3<<<512, 256>>>(bn2g, bn2b, fc3w);
    k_final<<<1, 256>>>(fc3b, bn3g, bn3b, targets, out, out_size);
}